// round 8
// baseline (speedup 1.0000x reference)
#include <cuda_runtime.h>
#include <math.h>

#define Cn 256
#define Hn 50
#define Wn 76
#define SCALE 0.0625f
#define PLANE (Hn * Wn)            // 3800
#define NUM_ROIS 128
#define PITCH 25                    // smem row pitch (odd-ish, conflict-light)
#define MAXH 24                     // union window provably <= 22 rows/cols
#define NWARP 8

__global__ __launch_bounds__(256)
void roipool_kernel(const float* __restrict__ feat,
                    const float* __restrict__ rois,
                    float* __restrict__ out)
{
    __shared__ float tile[NWARP][PITCH * MAXH];   // 8 x 600 floats = 19.2 KB
    __shared__ unsigned int win[49];              // abs coords: hs|he<<8|ws<<16|we<<24|empty<<31
    __shared__ int un[4];                         // hmin, hmax, wmin, wmax
    __shared__ int sbase;

    const int bid  = blockIdx.x;
    const int tid  = threadIdx.x;
    const int wid  = tid >> 5;
    const int lane = tid & 31;

    const int roi  = bid >> 5;            // 32 blocks per ROI
    const int ch   = ((bid & 31) << 3) + wid;   // this warp's channel

    if (tid == 0) { un[0] = 1 << 30; un[1] = -(1 << 30); un[2] = 1 << 30; un[3] = -(1 << 30); }
    __syncthreads();

    // ---- geometry: threads 0..48, one bin each ----
    if (tid < 49) {
        const int ph = tid / 7;
        const int pw = tid - ph * 7;
        const float* r = rois + roi * 5;
        int b  = (int)rintf(r[0]);
        int x1 = (int)rintf(r[1] * SCALE);
        int y1 = (int)rintf(r[2] * SCALE);
        int x2 = (int)rintf(r[3] * SCALE);
        int y2 = (int)rintf(r[4] * SCALE);

        int eh = max(y2 - y1 + 1, 1);
        int ew = max(x2 - x1 + 1, 1);

        // bit-exact emulation of XLA-CPU fast-math: extent * fl(1/7)
        const float R7 = 0.14285714285714285f;
        float bh = __fmul_rn((float)eh, R7);
        float bw = __fmul_rn((float)ew, R7);

        int hs = min(max((int)floorf(__fmul_rn((float)ph,       bh)) + y1, 0), Hn);
        int he = min(max((int)ceilf (__fmul_rn((float)(ph + 1), bh)) + y1, 0), Hn);
        int ws = min(max((int)floorf(__fmul_rn((float)pw,       bw)) + x1, 0), Wn);
        int we = min(max((int)ceilf (__fmul_rn((float)(pw + 1), bw)) + x1, 0), Wn);

        unsigned int empty = (hs >= he || ws >= we) ? 1u : 0u;
        if (!empty) {
            atomicMin(&un[0], hs); atomicMax(&un[1], he);
            atomicMin(&un[2], ws); atomicMax(&un[3], we);
        }
        win[tid] = (unsigned)hs | ((unsigned)he << 8) |
                   ((unsigned)ws << 16) | ((unsigned)we << 24) | (empty << 31);
        if (tid == 0) sbase = b * (Cn * PLANE);
    }
    __syncthreads();

    int hmin = un[0], wmin = un[2];
    int H = un[1] - hmin;
    int W = un[3] - wmin;
    if (H < 1) { hmin = 0; H = 1; }       // all bins empty (degenerate ROI)
    if (W < 1) { wmin = 0; W = 1; }
    H = min(H, MAXH);
    W = min(W, PITCH);

    // ---- stage this channel's union window into smem (row-coalesced) ----
    const float* plane = feat + sbase + ch * PLANE;
    float* t = tile[wid];
    for (int h = 0; h < H; ++h) {
        if (lane < W)
            t[h * PITCH + lane] = __ldg(plane + (hmin + h) * Wn + wmin + lane);
    }
    __syncwarp();

    // ---- compute 49 bin maxes from smem ----
    for (int bin = lane; bin < 49; bin += 32) {
        const unsigned int wv = win[bin];
        const unsigned int empty = wv >> 31;
        int hs, he, ws, we;
        if (empty) { hs = 0; he = 1; ws = 0; we = 1; }
        else {
            hs = (int)(wv & 0xff)         - hmin;
            he = (int)((wv >> 8)  & 0xff) - hmin;
            ws = (int)((wv >> 16) & 0xff) - wmin;
            we = (int)((wv >> 24) & 0x7f) - wmin;
        }

        const float* p0 = t + hs * PITCH + ws;
        const int H1 = he - 1 - hs;             // 0..3 (bin window <= 4x4)
        const int W1 = we - 1 - ws;
        const int dh1 = min(1, H1) * PITCH;
        const int dh2 = min(2, H1) * PITCH;
        const int dh3 = H1 * PITCH;
        const int dw1 = min(1, W1);
        const int dw2 = min(2, W1);
        const int dw3 = W1;

        float a0 = p0[0],   a1 = p0[dw1], a2 = p0[dw2], a3 = p0[dw3];
        const float* p1 = p0 + dh1;
        float b0 = p1[0],   b1 = p1[dw1], b2 = p1[dw2], b3 = p1[dw3];
        const float* p2 = p0 + dh2;
        float c0 = p2[0],   c1 = p2[dw1], c2 = p2[dw2], c3 = p2[dw3];
        const float* p3 = p0 + dh3;
        float d0 = p3[0],   d1 = p3[dw1], d2 = p3[dw2], d3 = p3[dw3];

        float r0 = fmaxf(fmaxf(a0, a1), fmaxf(a2, a3));
        float r1 = fmaxf(fmaxf(b0, b1), fmaxf(b2, b3));
        float r2 = fmaxf(fmaxf(c0, c1), fmaxf(c2, c3));
        float r3 = fmaxf(fmaxf(d0, d1), fmaxf(d2, d3));
        float m  = fmaxf(fmaxf(r0, r1), fmaxf(r2, r3));

        out[(roi * Cn + ch) * 49 + bin] = empty ? 0.0f : m;
    }
}

extern "C" void kernel_launch(void* const* d_in, const int* in_sizes, int n_in,
                              void* d_out, int out_size)
{
    const float* feat = (const float*)d_in[0];
    const float* rois = (const float*)d_in[1];
    float* out = (float*)d_out;

    roipool_kernel<<<NUM_ROIS * 32, 256>>>(feat, rois, out);
}